// round 1
// baseline (speedup 1.0000x reference)
#include <cuda_runtime.h>
#include <cuda_fp16.h>
#include <cstdint>

// Problem dims (fixed for this problem instance)
#define O_DIM 2048   // output features / GEMM N
#define I_DIM 2048   // input features  / GEMM K
#define M_DIM 4096   // B*S rows        / GEMM M
#define KC    256    // codebook entries
#define PQD   8      // codeword dim

// Scratch (device globals: allocation-free rule)
__device__ __align__(16) __half g_wq[O_DIM * I_DIM];  // quantized weight, fp16, [O][I] (K-contiguous)
__device__ __align__(16) __half g_x [M_DIM * I_DIM];  // x in fp16, [M][K]

// ---------------------------------------------------------------------------
// Kernel 1: convert x fp32 -> fp16
// ---------------------------------------------------------------------------
__global__ __launch_bounds__(256) void convert_x_kernel(const float* __restrict__ x) {
    int i = (blockIdx.x * 256 + threadIdx.x) * 8;
    float4 a = *reinterpret_cast<const float4*>(x + i);
    float4 b = *reinterpret_cast<const float4*>(x + i + 4);
    __half2 h0 = __floats2half2_rn(a.x, a.y);
    __half2 h1 = __floats2half2_rn(a.z, a.w);
    __half2 h2 = __floats2half2_rn(b.x, b.y);
    __half2 h3 = __floats2half2_rn(b.z, b.w);
    uint4 v;
    v.x = *reinterpret_cast<uint32_t*>(&h0);
    v.y = *reinterpret_cast<uint32_t*>(&h1);
    v.z = *reinterpret_cast<uint32_t*>(&h2);
    v.w = *reinterpret_cast<uint32_t*>(&h3);
    *reinterpret_cast<uint4*>(g_x + i) = v;
}

// ---------------------------------------------------------------------------
// Kernel 2: PQ quantize weight -> g_wq (fp16)
//   d2 = ||w/s||^2 - 2*(w/s)·c + ||c||^2 ; argmin (first index on ties)
//   wq = codebook[argmin] * s
// ---------------------------------------------------------------------------
__global__ __launch_bounds__(256) void quantize_kernel(const float* __restrict__ w,
                                                       const float* __restrict__ cb,
                                                       const float* __restrict__ rs) {
    __shared__ float4 scb[KC][2];
    __shared__ float  sc2[KC];
    int tid = threadIdx.x;
    {
        const float4* cb4 = reinterpret_cast<const float4*>(cb);
        float4 a = cb4[tid * 2];
        float4 b = cb4[tid * 2 + 1];
        scb[tid][0] = a;
        scb[tid][1] = b;
        float s = a.x * a.x;
        s = fmaf(a.y, a.y, s); s = fmaf(a.z, a.z, s); s = fmaf(a.w, a.w, s);
        s = fmaf(b.x, b.x, s); s = fmaf(b.y, b.y, s); s = fmaf(b.z, b.z, s); s = fmaf(b.w, b.w, s);
        sc2[tid] = s;
    }
    __syncthreads();

    int g    = blockIdx.x * 256 + tid;
    int flat = g * PQD;
    float scale = rs[flat >> 11];  // I_DIM = 2048, PQD divides row evenly

    float4 wa = *reinterpret_cast<const float4*>(w + flat);
    float4 wb = *reinterpret_cast<const float4*>(w + flat + 4);
    float x0 = wa.x / scale, x1 = wa.y / scale, x2 = wa.z / scale, x3 = wa.w / scale;
    float x4 = wb.x / scale, x5 = wb.y / scale, x6 = wb.z / scale, x7 = wb.w / scale;

    float xs = x0 * x0;
    xs = fmaf(x1, x1, xs); xs = fmaf(x2, x2, xs); xs = fmaf(x3, x3, xs);
    xs = fmaf(x4, x4, xs); xs = fmaf(x5, x5, xs); xs = fmaf(x6, x6, xs); xs = fmaf(x7, x7, xs);

    float best = 3.4e38f;
    int   bi   = 0;
#pragma unroll 4
    for (int k = 0; k < KC; k++) {
        float4 ca = scb[k][0];
        float4 cv = scb[k][1];
        float dot = x0 * ca.x;
        dot = fmaf(x1, ca.y, dot); dot = fmaf(x2, ca.z, dot); dot = fmaf(x3, ca.w, dot);
        dot = fmaf(x4, cv.x, dot); dot = fmaf(x5, cv.y, dot); dot = fmaf(x6, cv.z, dot); dot = fmaf(x7, cv.w, dot);
        float d2 = __fadd_rn(__fsub_rn(xs, __fmul_rn(2.0f, dot)), sc2[k]);
        if (d2 < best) { best = d2; bi = k; }
    }

    float4 qa = scb[bi][0];
    float4 qb = scb[bi][1];
    __half2 h0 = __floats2half2_rn(qa.x * scale, qa.y * scale);
    __half2 h1 = __floats2half2_rn(qa.z * scale, qa.w * scale);
    __half2 h2 = __floats2half2_rn(qb.x * scale, qb.y * scale);
    __half2 h3 = __floats2half2_rn(qb.z * scale, qb.w * scale);
    uint4 v;
    v.x = *reinterpret_cast<uint32_t*>(&h0);
    v.y = *reinterpret_cast<uint32_t*>(&h1);
    v.z = *reinterpret_cast<uint32_t*>(&h2);
    v.w = *reinterpret_cast<uint32_t*>(&h3);
    *reinterpret_cast<uint4*>(g_wq + flat) = v;
}

// ---------------------------------------------------------------------------
// Kernel 3: GEMM  out[M,N] = g_x[M,K] @ g_wq[N,K]^T + bias   (fp16 mma, f32 acc)
//   128x128x32 block tile, 8 warps (64x32 warp tiles), cp.async double buffer
// ---------------------------------------------------------------------------
#define BM 128
#define BN 128
#define BK 32
#define LDS_W 40   // BK + 8 halves padding -> conflict-free ldmatrix

__device__ __forceinline__ void cp_async16(uint32_t s, const void* g) {
    asm volatile("cp.async.cg.shared.global [%0], [%1], 16;\n" :: "r"(s), "l"(g));
}

__global__ __launch_bounds__(256) void gemm_kernel(const float* __restrict__ bias,
                                                   float* __restrict__ out) {
    __shared__ __half sA[2][BM * LDS_W];
    __shared__ __half sB[2][BN * LDS_W];

    int tid  = threadIdx.x;
    int lane = tid & 31;
    int wid  = tid >> 5;
    int bm0  = blockIdx.y * BM;
    int bn0  = blockIdx.x * BN;
    int wm   = (wid >> 2) * 64;  // warp M offset (2 warps in M)
    int wn   = (wid & 3) * 32;   // warp N offset (4 warps in N)

    const __half* gA = g_x  + (size_t)bm0 * I_DIM;
    const __half* gB = g_wq + (size_t)bn0 * I_DIM;

    uint32_t sA_u = (uint32_t)__cvta_generic_to_shared(sA);
    uint32_t sB_u = (uint32_t)__cvta_generic_to_shared(sB);

    float acc[4][4][4];
#pragma unroll
    for (int mi = 0; mi < 4; mi++)
#pragma unroll
        for (int ni = 0; ni < 4; ni++)
#pragma unroll
            for (int r = 0; r < 4; r++) acc[mi][ni][r] = 0.0f;

    int lr = tid >> 2;           // 0..63  (tile row, this thread loads rows lr and lr+64)
    int lc = (tid & 3) * 8;      // 0,8,16,24 halves

#define LOAD_TILE(buf, k0)                                                                     \
    do {                                                                                       \
        cp_async16(sA_u + (uint32_t)(((buf) * BM * LDS_W + lr * LDS_W + lc) * 2),              \
                   gA + (size_t)lr * I_DIM + (k0) + lc);                                       \
        cp_async16(sA_u + (uint32_t)(((buf) * BM * LDS_W + (lr + 64) * LDS_W + lc) * 2),       \
                   gA + (size_t)(lr + 64) * I_DIM + (k0) + lc);                                \
        cp_async16(sB_u + (uint32_t)(((buf) * BN * LDS_W + lr * LDS_W + lc) * 2),              \
                   gB + (size_t)lr * I_DIM + (k0) + lc);                                       \
        cp_async16(sB_u + (uint32_t)(((buf) * BN * LDS_W + (lr + 64) * LDS_W + lc) * 2),       \
                   gB + (size_t)(lr + 64) * I_DIM + (k0) + lc);                                \
        asm volatile("cp.async.commit_group;\n" ::: "memory");                                 \
    } while (0)

    const int KT = I_DIM / BK;  // 64
    LOAD_TILE(0, 0);

    for (int kt = 0; kt < KT; kt++) {
        int buf = kt & 1;
        if (kt + 1 < KT) {
            LOAD_TILE(buf ^ 1, (kt + 1) * BK);
            asm volatile("cp.async.wait_group 1;\n" ::: "memory");
        } else {
            asm volatile("cp.async.wait_group 0;\n" ::: "memory");
        }
        __syncthreads();

        uint32_t aBase = sA_u + (uint32_t)((buf * BM * LDS_W + (wm + (lane & 15)) * LDS_W + (lane >> 4) * 8) * 2);
        uint32_t bBase = sB_u + (uint32_t)((buf * BN * LDS_W + (wn + (lane & 7)) * LDS_W + ((lane >> 3) & 1) * 8) * 2);

#pragma unroll
        for (int ks = 0; ks < 2; ks++) {
            uint32_t a[4][4], b[4][2];
#pragma unroll
            for (int mi = 0; mi < 4; mi++) {
                uint32_t addr = aBase + (uint32_t)((mi * 16 * LDS_W + ks * 16) * 2);
                asm volatile("ldmatrix.sync.aligned.m8n8.x4.shared.b16 {%0,%1,%2,%3}, [%4];\n"
                             : "=r"(a[mi][0]), "=r"(a[mi][1]), "=r"(a[mi][2]), "=r"(a[mi][3])
                             : "r"(addr));
            }
#pragma unroll
            for (int ni = 0; ni < 4; ni++) {
                uint32_t addr = bBase + (uint32_t)((ni * 8 * LDS_W + ks * 16) * 2);
                asm volatile("ldmatrix.sync.aligned.m8n8.x2.shared.b16 {%0,%1}, [%2];\n"
                             : "=r"(b[ni][0]), "=r"(b[ni][1])
                             : "r"(addr));
            }
#pragma unroll
            for (int mi = 0; mi < 4; mi++)
#pragma unroll
                for (int ni = 0; ni < 4; ni++) {
                    asm volatile(
                        "mma.sync.aligned.m16n8k16.row.col.f32.f16.f16.f32 "
                        "{%0,%1,%2,%3}, {%4,%5,%6,%7}, {%8,%9}, {%0,%1,%2,%3};\n"
                        : "+f"(acc[mi][ni][0]), "+f"(acc[mi][ni][1]),
                          "+f"(acc[mi][ni][2]), "+f"(acc[mi][ni][3])
                        : "r"(a[mi][0]), "r"(a[mi][1]), "r"(a[mi][2]), "r"(a[mi][3]),
                          "r"(b[ni][0]), "r"(b[ni][1]));
                }
        }
        __syncthreads();
    }

    // Epilogue: += bias, write fp32
#pragma unroll
    for (int mi = 0; mi < 4; mi++) {
#pragma unroll
        for (int ni = 0; ni < 4; ni++) {
            int row = bm0 + wm + mi * 16 + (lane >> 2);
            int col = bn0 + wn + ni * 8 + (lane & 3) * 2;
            float b0 = bias[col];
            float b1 = bias[col + 1];
            float2 v0 = make_float2(acc[mi][ni][0] + b0, acc[mi][ni][1] + b1);
            float2 v1 = make_float2(acc[mi][ni][2] + b0, acc[mi][ni][3] + b1);
            *reinterpret_cast<float2*>(out + (size_t)row * O_DIM + col) = v0;
            *reinterpret_cast<float2*>(out + (size_t)(row + 8) * O_DIM + col) = v1;
        }
    }
}

// ---------------------------------------------------------------------------
extern "C" void kernel_launch(void* const* d_in, const int* in_sizes, int n_in,
                              void* d_out, int out_size) {
    const float* x    = (const float*)d_in[0];  // [4,1024,2048]
    const float* w    = (const float*)d_in[1];  // [2048,2048]
    const float* cb   = (const float*)d_in[2];  // [256,8]
    const float* rs   = (const float*)d_in[3];  // [2048,1]
    const float* bias = (const float*)d_in[4];  // [2048]
    float* out = (float*)d_out;

    convert_x_kernel<<<M_DIM * I_DIM / (256 * 8), 256>>>(x);
    quantize_kernel<<<(O_DIM * I_DIM / PQD) / 256, 256>>>(w, cb, rs);
    dim3 grid(O_DIM / BN, M_DIM / BM);
    gemm_kernel<<<grid, 256>>>(bias, out);
}